// round 11
// baseline (speedup 1.0000x reference)
#include <cuda_runtime.h>
#include <cuda_fp16.h>
#include <cstdint>
#include <math.h>

#define D_MODEL 1024
#define D_FF    4096
#define NEXP    8
#define MAXN    8192
#define HROWS   (2*MAXN + 256)

#define BM 128
#define BN 128
#define BK 32                      // halfs per stage along K
#define NTHREADS 128
#define A_STRIDE_B 80              // bytes per A smem row (64 data + 16 pad)
#define A_TILE_B (BM * A_STRIDE_B) // 10240
#define B_ROW_B  (BN * 2)          // 256 bytes per k-row (16 chunks)
#define B_TILE_B (BK * B_ROW_B)    // 8192
#define STAGE_B  (A_TILE_B + B_TILE_B)   // 18432
#define NSTAGE 6
#define DSMEM_BYTES (NSTAGE * STAGE_B)   // 110592 -> 2 CTAs/SM
#define KSPLIT2 4                  // K-split factor for GEMM2

// ---------------- scratch (static device globals; no allocation) ----------------
__device__ int    g_cnt[NEXP];
__device__ int    g_base[NEXP];
__device__ int    g_tok[NEXP * MAXN];
__device__ float  g_gate[NEXP * MAXN];
__device__ __half g_xh [(size_t)MAXN * D_MODEL];
__device__ __half g_W1h[(size_t)NEXP * D_MODEL * D_FF];
__device__ __half g_W2h[(size_t)NEXP * D_FF * D_MODEL];
__device__ __half g_Hh [(size_t)HROWS * D_FF];

// ---------------- helpers ----------------
__device__ __forceinline__ void mma_f16(float c[4], const uint32_t a[4], const uint32_t b[2]) {
    asm volatile(
        "mma.sync.aligned.m16n8k16.row.col.f32.f16.f16.f32 "
        "{%0,%1,%2,%3}, {%4,%5,%6,%7}, {%8,%9}, {%0,%1,%2,%3};"
        : "+f"(c[0]), "+f"(c[1]), "+f"(c[2]), "+f"(c[3])
        : "r"(a[0]), "r"(a[1]), "r"(a[2]), "r"(a[3]), "r"(b[0]), "r"(b[1]));
}
__device__ __forceinline__ void ldsm_x4(uint32_t& r0, uint32_t& r1, uint32_t& r2, uint32_t& r3,
                                        uint32_t saddr) {
    asm volatile("ldmatrix.sync.aligned.m8n8.x4.shared.b16 {%0,%1,%2,%3}, [%4];"
                 : "=r"(r0), "=r"(r1), "=r"(r2), "=r"(r3) : "r"(saddr));
}
__device__ __forceinline__ void ldsm_x4_t(uint32_t& r0, uint32_t& r1, uint32_t& r2, uint32_t& r3,
                                          uint32_t saddr) {
    asm volatile("ldmatrix.sync.aligned.m8n8.x4.trans.shared.b16 {%0,%1,%2,%3}, [%4];"
                 : "=r"(r0), "=r"(r1), "=r"(r2), "=r"(r3) : "r"(saddr));
}
__device__ __forceinline__ void cp16(uint32_t saddr, const void* g) {
    asm volatile("cp.async.cg.shared.global [%0], [%1], 16;" :: "r"(saddr), "l"(g) : "memory");
}
__device__ __forceinline__ void cp_commit() { asm volatile("cp.async.commit_group;" ::: "memory"); }
__device__ __forceinline__ void cp_wait2()  { asm volatile("cp.async.wait_group 2;" ::: "memory"); }

__device__ __forceinline__ float gelu_exact(float v) {
    return 0.5f * v * (1.0f + erff(v * 0.7071067811865476f));
}

// ---------------- tiny init: counters only ----------------
__global__ void init_kernel() {
    if (threadIdx.x < NEXP) g_cnt[threadIdx.x] = 0;
}

// ---------------- fused prep: router | zero out | half x | half W1/W2 ----------------
__global__ void prep_kernel(float* __restrict__ out, int nout,
                            const float* __restrict__ x, int N,
                            const float* __restrict__ Wr, const float* __restrict__ br,
                            const float* __restrict__ W1, const float* __restrict__ W2) {
    const int b = blockIdx.x;
    const int tid = threadIdx.x;

    if (b < 1024) {
        // ---- router: 8 warps per block, 1 token per warp ----
        int wg = b * 8 + (tid >> 5);
        int lane = tid & 31;
        if (wg >= N) return;
        const float* xr = x + (size_t)wg * D_MODEL;

        float acc[NEXP];
#pragma unroll
        for (int e = 0; e < NEXP; e++) acc[e] = 0.0f;
#pragma unroll
        for (int it = 0; it < D_MODEL / 128; it++) {
            int d = it * 128 + lane * 4;
            float4 xv = *reinterpret_cast<const float4*>(xr + d);
            const float xa[4] = { xv.x, xv.y, xv.z, xv.w };
#pragma unroll
            for (int q = 0; q < 4; q++) {
                const float4* w4 = reinterpret_cast<const float4*>(Wr + (size_t)(d + q) * NEXP);
                float4 w0 = w4[0], w1 = w4[1];
                acc[0] += xa[q] * w0.x; acc[1] += xa[q] * w0.y;
                acc[2] += xa[q] * w0.z; acc[3] += xa[q] * w0.w;
                acc[4] += xa[q] * w1.x; acc[5] += xa[q] * w1.y;
                acc[6] += xa[q] * w1.z; acc[7] += xa[q] * w1.w;
            }
        }
#pragma unroll
        for (int off = 16; off; off >>= 1)
#pragma unroll
            for (int e = 0; e < NEXP; e++)
                acc[e] += __shfl_xor_sync(0xffffffffu, acc[e], off);

        if (lane == 0) {
            float l[NEXP];
#pragma unroll
            for (int e = 0; e < NEXP; e++) l[e] = acc[e] + br[e];
            float m = l[0];
#pragma unroll
            for (int e = 1; e < NEXP; e++) m = fmaxf(m, l[e]);
            float p[NEXP], se = 0.0f;
#pragma unroll
            for (int e = 0; e < NEXP; e++) { p[e] = expf(l[e] - m); se += p[e]; }
            int i1 = 0; float v1 = p[0];
#pragma unroll
            for (int e = 1; e < NEXP; e++) if (p[e] > v1) { v1 = p[e]; i1 = e; }
            int i2 = -1; float v2 = -1.0f;
#pragma unroll
            for (int e = 0; e < NEXP; e++) if (e != i1 && p[e] > v2) { v2 = p[e]; i2 = e; }
            float p1 = v1 / se, p2 = v2 / se;
            float inv = 1.0f / (p1 + p2 + 1e-9f);
            float w1 = p1 * inv, w2 = p2 * inv;

            int pos = atomicAdd(&g_cnt[i1], 1);
            g_tok[i1 * MAXN + pos] = wg;  g_gate[i1 * MAXN + pos] = w1;
            pos = atomicAdd(&g_cnt[i2], 1);
            g_tok[i2 * MAXN + pos] = wg;  g_gate[i2 * MAXN + pos] = w2;
        }
    } else if (b < 1536) {
        int n4 = nout >> 2;
        float4 z = make_float4(0.f, 0.f, 0.f, 0.f);
        for (int i = (b - 1024) * 256 + tid; i < n4; i += 512 * 256)
            reinterpret_cast<float4*>(out)[i] = z;
    } else if (b < 2048) {
        int n4 = N * D_MODEL / 4;
        for (int i = (b - 1536) * 256 + tid; i < n4; i += 512 * 256) {
            float4 v = reinterpret_cast<const float4*>(x)[i];
            __half2 h0 = __floats2half2_rn(v.x, v.y);
            __half2 h1 = __floats2half2_rn(v.z, v.w);
            uint2 u = { *(uint32_t*)&h0, *(uint32_t*)&h1 };
            reinterpret_cast<uint2*>(g_xh)[i] = u;
        }
    } else {
        const int n4 = NEXP * D_MODEL * D_FF / 4;
        for (int i = (b - 2048) * 256 + tid; i < n4; i += 4096 * 256) {
            float4 v = reinterpret_cast<const float4*>(W1)[i];
            __half2 a0 = __floats2half2_rn(v.x, v.y);
            __half2 a1 = __floats2half2_rn(v.z, v.w);
            uint2 u = { *(uint32_t*)&a0, *(uint32_t*)&a1 };
            reinterpret_cast<uint2*>(g_W1h)[i] = u;
            float4 w = reinterpret_cast<const float4*>(W2)[i];
            __half2 b0 = __floats2half2_rn(w.x, w.y);
            __half2 b1 = __floats2half2_rn(w.z, w.w);
            uint2 t = { *(uint32_t*)&b0, *(uint32_t*)&b1 };
            reinterpret_cast<uint2*>(g_W2h)[i] = t;
        }
    }
}

__global__ void scan_kernel() {
    int b = 0;
#pragma unroll
    for (int e = 0; e < NEXP; e++) { g_base[e] = b; b += g_cnt[e]; }
}

// ---------------- grouped GEMM: 2 k-tiles per barrier, 6-stage pipeline, optional K-split ----------------
template<int KD, int ND, bool PHASE1, int KSPLIT>
__global__ void __launch_bounds__(NTHREADS, 2)
moe_gemm_kernel(const float* __restrict__ bias, float* __restrict__ Out) {
    const int e  = blockIdx.z;
    const int Me = g_cnt[e];
    const int tm    = blockIdx.y / KSPLIT;
    const int split = blockIdx.y % KSPLIT;
    if (tm * BM >= Me) return;
    const int tn   = blockIdx.x;
    const int base = g_base[e];

    extern __shared__ char smem[];
    const uint32_t sbase = (uint32_t)__cvta_generic_to_shared(smem);

    const int tid = threadIdx.x;
    const __half* Aglob = PHASE1 ? g_xh : g_Hh;
    const __half* We    = (PHASE1 ? g_W1h : g_W2h) + (size_t)e * KD * ND;

    constexpr int KT_ALL = KD / BK;
    constexpr int KT = KT_ALL / KSPLIT;       // k-tiles handled by this CTA (even)
    const int k0 = split * KT * BK;           // element offset in K

    // ---- A loader: 4 chunks of 16B per thread (128 rows x 4 chunks)
    const __half* agp[4]; uint32_t aso[4];
#pragma unroll
    for (int j = 0; j < 4; j++) {
        int cid = tid + NTHREADS * j;
        int row = cid >> 2, ch = cid & 3;
        int m = tm * BM + row;
        size_t arow;
        if (PHASE1) arow = (size_t)g_tok[e * MAXN + (m < Me ? m : 0)];
        else { long r = (long)base + m; if (r >= HROWS) r = 0; arow = (size_t)r; }
        agp[j] = Aglob + arow * KD + k0 + ch * 8;
        aso[j] = row * A_STRIDE_B + ch * 16;
    }
    // ---- B loader: 4 chunks of 16B per thread (32 krows x 16 chunks)
    const __half* bgp[4]; uint32_t bso[4];
#pragma unroll
    for (int j = 0; j < 4; j++) {
        int cid = tid + NTHREADS * j;
        int krow = cid >> 4, c = cid & 15;
        bgp[j] = We + (size_t)(k0 + krow) * ND + tn * BN + c * 8;
        bso[j] = A_TILE_B + krow * B_ROW_B + ((c ^ (krow & 7)) << 4);
    }

    const int warp = tid >> 5, lane = tid & 31;
    const int wr = warp >> 1, wc = warp & 1;   // 2x2 warp grid; warp tile 64x64

    uint32_t a_addr[4];
#pragma unroll
    for (int mt = 0; mt < 4; mt++) {
        int row = wr * 64 + mt * 16 + (lane & 15);
        a_addr[mt] = row * A_STRIDE_B + (lane >> 4) * 16;
    }
    uint32_t b_addr[2][4];
#pragma unroll
    for (int ks = 0; ks < 2; ks++)
#pragma unroll
        for (int nb = 0; nb < 4; nb++) {
            int krow = ks * 16 + (lane & 15);
            int nc = wc * 8 + nb * 2 + (lane >> 4);
            b_addr[ks][nb] = A_TILE_B + krow * B_ROW_B + ((nc ^ (krow & 7)) << 4);
        }

    float c[4][8][4];
#pragma unroll
    for (int i = 0; i < 4; i++)
#pragma unroll
        for (int j = 0; j < 8; j++)
#pragma unroll
            for (int k = 0; k < 4; k++) c[i][j][k] = 0.0f;

    // prologue: stages 0..3 (4 groups)
#pragma unroll
    for (int s = 0; s < 4; s++) {
        uint32_t sb = sbase + s * STAGE_B;
        size_t ko = (size_t)s * BK;
#pragma unroll
        for (int j = 0; j < 4; j++) cp16(sb + aso[j], agp[j] + ko);
#pragma unroll
        for (int j = 0; j < 4; j++) cp16(sb + bso[j], bgp[j] + ko * ND);
        cp_commit();
    }

    int slot = 0;
    for (int kt = 0; kt < KT; kt += 2) {
        cp_wait2();
        __syncthreads();

        const int slot1 = (slot + 1 == NSTAGE) ? 0 : slot + 1;
        const uint32_t sb0 = sbase + slot * STAGE_B;
        const uint32_t sb1 = sbase + slot1 * STAGE_B;

        // ======== k-tile kt (slot) ========
        uint32_t af[2][4][4], bf[2][4][4];
#pragma unroll
        for (int ks = 0; ks < 2; ks++)
#pragma unroll
            for (int mt = 0; mt < 4; mt++)
                ldsm_x4(af[ks][mt][0], af[ks][mt][1], af[ks][mt][2], af[ks][mt][3],
                        sb0 + a_addr[mt] + ks * 32);
#pragma unroll
        for (int ks = 0; ks < 2; ks++)
#pragma unroll
            for (int nb = 0; nb < 4; nb++)
                ldsm_x4_t(bf[ks][nb][0], bf[ks][nb][1], bf[ks][nb][2], bf[ks][nb][3],
                          sb0 + b_addr[ks][nb]);
        {
            int pk = kt + 4;
            if (pk < KT) {
                int st = slot + 4; if (st >= NSTAGE) st -= NSTAGE;
                uint32_t sp = sbase + st * STAGE_B;
                size_t ko = (size_t)pk * BK;
#pragma unroll
                for (int j = 0; j < 4; j++) cp16(sp + aso[j], agp[j] + ko);
#pragma unroll
                for (int j = 0; j < 4; j++) cp16(sp + bso[j], bgp[j] + ko * ND);
            }
            cp_commit();
        }
#pragma unroll
        for (int ks = 0; ks < 2; ks++)
#pragma unroll
            for (int mt = 0; mt < 4; mt++)
#pragma unroll
                for (int nb = 0; nb < 4; nb++) {
                    mma_f16(c[mt][nb * 2 + 0], af[ks][mt], &bf[ks][nb][0]);
                    mma_f16(c[mt][nb * 2 + 1], af[ks][mt], &bf[ks][nb][2]);
                }

        // ======== k-tile kt+1 (slot1) ========
#pragma unroll
        for (int ks = 0; ks < 2; ks++)
#pragma unroll
            for (int mt = 0; mt < 4; mt++)
                ldsm_x4(af[ks][mt][0], af[ks][mt][1], af[ks][mt][2], af[ks][mt][3],
                        sb1 + a_addr[mt] + ks * 32);
#pragma unroll
        for (int ks = 0; ks < 2; ks++)
#pragma unroll
            for (int nb = 0; nb < 4; nb++)
                ldsm_x4_t(bf[ks][nb][0], bf[ks][nb][1], bf[ks][nb][2], bf[ks][nb][3],
                          sb1 + b_addr[ks][nb]);
        {
            int pk = kt + 5;
            if (pk < KT) {
                int st = slot + 5; if (st >= NSTAGE) st -= NSTAGE;
                uint32_t sp = sbase + st * STAGE_B;
                size_t ko = (size_t)pk * BK;
#pragma unroll
                for (int j = 0; j < 4; j++) cp16(sp + aso[j], agp[j] + ko);
#pragma unroll
                for (int j = 0; j < 4; j++) cp16(sp + bso[j], bgp[j] + ko * ND);
            }
            cp_commit();
        }
#pragma unroll
        for (int ks = 0; ks < 2; ks++)
#pragma unroll
            for (int mt = 0; mt < 4; mt++)
#pragma unroll
                for (int nb = 0; nb < 4; nb++) {
                    mma_f16(c[mt][nb * 2 + 0], af[ks][mt], &bf[ks][nb][0]);
                    mma_f16(c[mt][nb * 2 + 1], af[ks][mt], &bf[ks][nb][2]);
                }

        slot += 2; if (slot >= NSTAGE) slot -= NSTAGE;
    }

    // ---- epilogue ----
    const float* be = bias + (size_t)e * ND;
    const int bofs = tn * BN;
    const bool addb = (split == 0);
#pragma unroll
    for (int mt = 0; mt < 4; mt++) {
        int mrow = tm * BM + wr * 64 + mt * 16 + (lane >> 2);
#pragma unroll
        for (int half = 0; half < 2; half++) {
            int m = mrow + half * 8;
            if (m >= Me) continue;
            if (PHASE1) {
                __half* Hr = g_Hh + (size_t)(base + m) * ND + bofs;
#pragma unroll
                for (int nt = 0; nt < 8; nt++) {
                    int n = wc * 64 + nt * 8 + (lane & 3) * 2;
                    float v0 = c[mt][nt][half * 2 + 0] + be[bofs + n];
                    float v1 = c[mt][nt][half * 2 + 1] + be[bofs + n + 1];
                    __half2 h = __floats2half2_rn(gelu_exact(v0), gelu_exact(v1));
                    *reinterpret_cast<uint32_t*>(Hr + n) = *(uint32_t*)&h;
                }
            } else {
                int tok = g_tok[e * MAXN + m];
                float g = g_gate[e * MAXN + m];
                float* Or = Out + (size_t)tok * ND + bofs;
#pragma unroll
                for (int nt = 0; nt < 8; nt++) {
                    int n = wc * 64 + nt * 8 + (lane & 3) * 2;
                    float b0 = addb ? be[bofs + n]     : 0.0f;
                    float b1 = addb ? be[bofs + n + 1] : 0.0f;
                    atomicAdd(&Or[n],     g * (c[mt][nt][half * 2 + 0] + b0));
                    atomicAdd(&Or[n + 1], g * (c[mt][nt][half * 2 + 1] + b1));
                }
            }
        }
    }
}

// ---------------- launch ----------------
extern "C" void kernel_launch(void* const* d_in, const int* in_sizes, int n_in,
                              void* d_out, int out_size) {
    const float* x  = (const float*)d_in[0];
    const float* Wr = (const float*)d_in[1];
    const float* br = (const float*)d_in[2];
    const float* W1 = (const float*)d_in[3];
    const float* b1 = (const float*)d_in[4];
    const float* W2 = (const float*)d_in[5];
    const float* b2 = (const float*)d_in[6];
    float* out = (float*)d_out;

    int N = in_sizes[0] / D_MODEL;   // 8192 tokens
    if (N > MAXN) N = MAXN;

    cudaFuncSetAttribute(moe_gemm_kernel<D_MODEL, D_FF, true, 1>,
                         cudaFuncAttributeMaxDynamicSharedMemorySize, DSMEM_BYTES);
    cudaFuncSetAttribute(moe_gemm_kernel<D_FF, D_MODEL, false, KSPLIT2>,
                         cudaFuncAttributeMaxDynamicSharedMemorySize, DSMEM_BYTES);

    init_kernel<<<1, 32>>>();
    prep_kernel<<<6144, 256>>>(out, out_size, x, N, Wr, br, W1, W2);
    scan_kernel<<<1, 1>>>();

    dim3 g1(D_FF / BN, (N + BM - 1) / BM, NEXP);
    moe_gemm_kernel<D_MODEL, D_FF, true, 1><<<g1, NTHREADS, DSMEM_BYTES>>>(b1, nullptr);

    dim3 g2(D_MODEL / BN, ((N + BM - 1) / BM) * KSPLIT2, NEXP);
    moe_gemm_kernel<D_FF, D_MODEL, false, KSPLIT2><<<g2, NTHREADS, DSMEM_BYTES>>>(b2, out);
}

// round 12
// speedup vs baseline: 1.0774x; 1.0774x over previous
#include <cuda_runtime.h>
#include <cuda_fp16.h>
#include <cstdint>
#include <math.h>

#define D_MODEL 1024
#define D_FF    4096
#define NEXP    8
#define MAXN    8192
#define HROWS   (2*MAXN + 256)

#define BM 128
#define BN 128
#define BK 32                      // halfs per stage along K
#define NTHREADS 128
#define A_STRIDE_B 80              // bytes per A smem row (64 data + 16 pad)
#define A_TILE_B (BM * A_STRIDE_B) // 10240
#define B_ROW_B  (BN * 2)          // 256 bytes per k-row (16 chunks)
#define B_TILE_B (BK * B_ROW_B)    // 8192
#define STAGE_B  (A_TILE_B + B_TILE_B)   // 18432
#define NSTAGE 6
#define DSMEM_BYTES (NSTAGE * STAGE_B)   // 110592 -> 2 CTAs/SM

// ---------------- scratch (static device globals; no allocation) ----------------
__device__ int    g_cnt[NEXP];
__device__ int    g_base[NEXP];
__device__ int    g_tok[NEXP * MAXN];
__device__ float  g_gate[NEXP * MAXN];
__device__ __half g_xh [(size_t)MAXN * D_MODEL];
__device__ __half g_W1h[(size_t)NEXP * D_MODEL * D_FF];
__device__ __half g_W2h[(size_t)NEXP * D_FF * D_MODEL];
__device__ __half g_Hh [(size_t)HROWS * D_FF];

// ---------------- helpers ----------------
__device__ __forceinline__ void mma_f16(float c[4], const uint32_t a[4], const uint32_t b[2]) {
    asm volatile(
        "mma.sync.aligned.m16n8k16.row.col.f32.f16.f16.f32 "
        "{%0,%1,%2,%3}, {%4,%5,%6,%7}, {%8,%9}, {%0,%1,%2,%3};"
        : "+f"(c[0]), "+f"(c[1]), "+f"(c[2]), "+f"(c[3])
        : "r"(a[0]), "r"(a[1]), "r"(a[2]), "r"(a[3]), "r"(b[0]), "r"(b[1]));
}
__device__ __forceinline__ void ldsm_x4(uint32_t& r0, uint32_t& r1, uint32_t& r2, uint32_t& r3,
                                        uint32_t saddr) {
    asm volatile("ldmatrix.sync.aligned.m8n8.x4.shared.b16 {%0,%1,%2,%3}, [%4];"
                 : "=r"(r0), "=r"(r1), "=r"(r2), "=r"(r3) : "r"(saddr));
}
__device__ __forceinline__ void ldsm_x4_t(uint32_t& r0, uint32_t& r1, uint32_t& r2, uint32_t& r3,
                                          uint32_t saddr) {
    asm volatile("ldmatrix.sync.aligned.m8n8.x4.trans.shared.b16 {%0,%1,%2,%3}, [%4];"
                 : "=r"(r0), "=r"(r1), "=r"(r2), "=r"(r3) : "r"(saddr));
}
__device__ __forceinline__ void cp16(uint32_t saddr, const void* g) {
    asm volatile("cp.async.cg.shared.global [%0], [%1], 16;" :: "r"(saddr), "l"(g) : "memory");
}
__device__ __forceinline__ void cp_commit() { asm volatile("cp.async.commit_group;" ::: "memory"); }
__device__ __forceinline__ void cp_wait2()  { asm volatile("cp.async.wait_group 2;" ::: "memory"); }

__device__ __forceinline__ float gelu_exact(float v) {
    return 0.5f * v * (1.0f + erff(v * 0.7071067811865476f));
}

// ---------------- tiny init: counters only ----------------
__global__ void init_kernel() {
    if (threadIdx.x < NEXP) g_cnt[threadIdx.x] = 0;
}

// ---------------- fused prep: router | zero out | half x | half W1 ----------------
// block ranges: [0,1024) router, [1024,1536) zero, [1536,2048) half_x, [2048,4096) half_W1
__global__ void prep_kernel(float* __restrict__ out, int nout,
                            const float* __restrict__ x, int N,
                            const float* __restrict__ Wr, const float* __restrict__ br,
                            const float* __restrict__ W1) {
    const int b = blockIdx.x;
    const int tid = threadIdx.x;

    if (b < 1024) {
        // ---- router: 8 warps per block, 1 token per warp ----
        int wg = b * 8 + (tid >> 5);
        int lane = tid & 31;
        if (wg >= N) return;
        const float* xr = x + (size_t)wg * D_MODEL;

        float acc[NEXP];
#pragma unroll
        for (int e = 0; e < NEXP; e++) acc[e] = 0.0f;
#pragma unroll
        for (int it = 0; it < D_MODEL / 128; it++) {
            int d = it * 128 + lane * 4;
            float4 xv = *reinterpret_cast<const float4*>(xr + d);
            const float xa[4] = { xv.x, xv.y, xv.z, xv.w };
#pragma unroll
            for (int q = 0; q < 4; q++) {
                const float4* w4 = reinterpret_cast<const float4*>(Wr + (size_t)(d + q) * NEXP);
                float4 w0 = w4[0], w1 = w4[1];
                acc[0] += xa[q] * w0.x; acc[1] += xa[q] * w0.y;
                acc[2] += xa[q] * w0.z; acc[3] += xa[q] * w0.w;
                acc[4] += xa[q] * w1.x; acc[5] += xa[q] * w1.y;
                acc[6] += xa[q] * w1.z; acc[7] += xa[q] * w1.w;
            }
        }
#pragma unroll
        for (int off = 16; off; off >>= 1)
#pragma unroll
            for (int e = 0; e < NEXP; e++)
                acc[e] += __shfl_xor_sync(0xffffffffu, acc[e], off);

        if (lane == 0) {
            float l[NEXP];
#pragma unroll
            for (int e = 0; e < NEXP; e++) l[e] = acc[e] + br[e];
            float m = l[0];
#pragma unroll
            for (int e = 1; e < NEXP; e++) m = fmaxf(m, l[e]);
            float p[NEXP], se = 0.0f;
#pragma unroll
            for (int e = 0; e < NEXP; e++) { p[e] = expf(l[e] - m); se += p[e]; }
            int i1 = 0; float v1 = p[0];
#pragma unroll
            for (int e = 1; e < NEXP; e++) if (p[e] > v1) { v1 = p[e]; i1 = e; }
            int i2 = -1; float v2 = -1.0f;
#pragma unroll
            for (int e = 0; e < NEXP; e++) if (e != i1 && p[e] > v2) { v2 = p[e]; i2 = e; }
            float p1 = v1 / se, p2 = v2 / se;
            float inv = 1.0f / (p1 + p2 + 1e-9f);
            float w1 = p1 * inv, w2 = p2 * inv;

            int pos = atomicAdd(&g_cnt[i1], 1);
            g_tok[i1 * MAXN + pos] = wg;  g_gate[i1 * MAXN + pos] = w1;
            pos = atomicAdd(&g_cnt[i2], 1);
            g_tok[i2 * MAXN + pos] = wg;  g_gate[i2 * MAXN + pos] = w2;
        }
    } else if (b < 1536) {
        int n4 = nout >> 2;
        float4 z = make_float4(0.f, 0.f, 0.f, 0.f);
        for (int i = (b - 1024) * 256 + tid; i < n4; i += 512 * 256)
            reinterpret_cast<float4*>(out)[i] = z;
    } else if (b < 2048) {
        int n4 = N * D_MODEL / 4;
        for (int i = (b - 1536) * 256 + tid; i < n4; i += 512 * 256) {
            float4 v = reinterpret_cast<const float4*>(x)[i];
            __half2 h0 = __floats2half2_rn(v.x, v.y);
            __half2 h1 = __floats2half2_rn(v.z, v.w);
            uint2 u = { *(uint32_t*)&h0, *(uint32_t*)&h1 };
            reinterpret_cast<uint2*>(g_xh)[i] = u;
        }
    } else {
        // ---- W1 -> half only (W2 converted inside GEMM1 launch) ----
        const int n4 = NEXP * D_MODEL * D_FF / 4;
        for (int i = (b - 2048) * 256 + tid; i < n4; i += 2048 * 256) {
            float4 v = reinterpret_cast<const float4*>(W1)[i];
            __half2 a0 = __floats2half2_rn(v.x, v.y);
            __half2 a1 = __floats2half2_rn(v.z, v.w);
            uint2 u = { *(uint32_t*)&a0, *(uint32_t*)&a1 };
            reinterpret_cast<uint2*>(g_W1h)[i] = u;
        }
    }
}

__global__ void scan_kernel() {
    int b = 0;
#pragma unroll
    for (int e = 0; e < NEXP; e++) { g_base[e] = b; b += g_cnt[e]; }
}

// ---------------- grouped GEMM: 2 k-tiles per barrier, 6-stage pipeline ----------------
// PHASE1 additionally carries 512 converter CTAs (blockIdx.x == gridDim.x-1) that
// convert W2 -> g_W2h, overlapping with GEMM1 compute. Wsrc is W2 in phase1.
template<int KD, int ND, bool PHASE1>
__global__ void __launch_bounds__(NTHREADS, 2)
moe_gemm_kernel(const float* __restrict__ bias, float* __restrict__ Out,
                const float* __restrict__ Wsrc) {
    const int e  = blockIdx.z;
    const int tn = blockIdx.x;

    if (PHASE1 && tn == (ND / BN)) {
        // ---- W2 converter CTA: slice (blockIdx.y + 64*e) of 512 ----
        const int sid = blockIdx.y + 64 * e;
        const int per = NEXP * D_MODEL * D_FF / 4 / 512;   // 16384 float4 per slice
        int i0 = sid * per + threadIdx.x;
#pragma unroll 4
        for (int i = i0; i < sid * per + per; i += NTHREADS) {
            float4 w = reinterpret_cast<const float4*>(Wsrc)[i];
            __half2 b0 = __floats2half2_rn(w.x, w.y);
            __half2 b1 = __floats2half2_rn(w.z, w.w);
            uint2 t = { *(uint32_t*)&b0, *(uint32_t*)&b1 };
            reinterpret_cast<uint2*>(g_W2h)[i] = t;
        }
        return;
    }

    const int Me = g_cnt[e];
    const int tm = blockIdx.y;
    if (tm * BM >= Me) return;
    const int base = g_base[e];

    extern __shared__ char smem[];
    const uint32_t sbase = (uint32_t)__cvta_generic_to_shared(smem);

    const int tid = threadIdx.x;
    const __half* Aglob = PHASE1 ? g_xh : g_Hh;
    const __half* We    = (PHASE1 ? g_W1h : g_W2h) + (size_t)e * KD * ND;

    // ---- A loader: 4 chunks of 16B per thread (128 rows x 4 chunks)
    const __half* agp[4]; uint32_t aso[4];
#pragma unroll
    for (int j = 0; j < 4; j++) {
        int cid = tid + NTHREADS * j;
        int row = cid >> 2, ch = cid & 3;
        int m = tm * BM + row;
        size_t arow;
        if (PHASE1) arow = (size_t)g_tok[e * MAXN + (m < Me ? m : 0)];
        else { long r = (long)base + m; if (r >= HROWS) r = 0; arow = (size_t)r; }
        agp[j] = Aglob + arow * KD + ch * 8;
        aso[j] = row * A_STRIDE_B + ch * 16;
    }
    // ---- B loader: 4 chunks of 16B per thread (32 krows x 16 chunks)
    const __half* bgp[4]; uint32_t bso[4];
#pragma unroll
    for (int j = 0; j < 4; j++) {
        int cid = tid + NTHREADS * j;
        int krow = cid >> 4, c = cid & 15;
        bgp[j] = We + (size_t)krow * ND + tn * BN + c * 8;
        bso[j] = A_TILE_B + krow * B_ROW_B + ((c ^ (krow & 7)) << 4);
    }

    constexpr int KT = KD / BK;
    const int warp = tid >> 5, lane = tid & 31;
    const int wr = warp >> 1, wc = warp & 1;   // 2x2 warp grid; warp tile 64x64

    uint32_t a_addr[4];
#pragma unroll
    for (int mt = 0; mt < 4; mt++) {
        int row = wr * 64 + mt * 16 + (lane & 15);
        a_addr[mt] = row * A_STRIDE_B + (lane >> 4) * 16;
    }
    uint32_t b_addr[2][4];
#pragma unroll
    for (int ks = 0; ks < 2; ks++)
#pragma unroll
        for (int nb = 0; nb < 4; nb++) {
            int krow = ks * 16 + (lane & 15);
            int nc = wc * 8 + nb * 2 + (lane >> 4);
            b_addr[ks][nb] = A_TILE_B + krow * B_ROW_B + ((nc ^ (krow & 7)) << 4);
        }

    float c[4][8][4];
#pragma unroll
    for (int i = 0; i < 4; i++)
#pragma unroll
        for (int j = 0; j < 8; j++)
#pragma unroll
            for (int k = 0; k < 4; k++) c[i][j][k] = 0.0f;

    // prologue: stages 0..3 (4 groups)
#pragma unroll
    for (int s = 0; s < 4; s++) {
        uint32_t sb = sbase + s * STAGE_B;
        size_t ko = (size_t)s * BK;
#pragma unroll
        for (int j = 0; j < 4; j++) cp16(sb + aso[j], agp[j] + ko);
#pragma unroll
        for (int j = 0; j < 4; j++) cp16(sb + bso[j], bgp[j] + ko * ND);
        cp_commit();
    }

    int slot = 0;
    for (int kt = 0; kt < KT; kt += 2) {
        cp_wait2();
        __syncthreads();

        const int slot1 = (slot + 1 == NSTAGE) ? 0 : slot + 1;
        const uint32_t sb0 = sbase + slot * STAGE_B;
        const uint32_t sb1 = sbase + slot1 * STAGE_B;

        // ======== k-tile kt (slot) ========
        uint32_t af[2][4][4], bf[2][4][4];
#pragma unroll
        for (int ks = 0; ks < 2; ks++)
#pragma unroll
            for (int mt = 0; mt < 4; mt++)
                ldsm_x4(af[ks][mt][0], af[ks][mt][1], af[ks][mt][2], af[ks][mt][3],
                        sb0 + a_addr[mt] + ks * 32);
#pragma unroll
        for (int ks = 0; ks < 2; ks++)
#pragma unroll
            for (int nb = 0; nb < 4; nb++)
                ldsm_x4_t(bf[ks][nb][0], bf[ks][nb][1], bf[ks][nb][2], bf[ks][nb][3],
                          sb0 + b_addr[ks][nb]);
        {
            int pk = kt + 4;
            if (pk < KT) {
                int st = slot + 4; if (st >= NSTAGE) st -= NSTAGE;
                uint32_t sp = sbase + st * STAGE_B;
                size_t ko = (size_t)pk * BK;
#pragma unroll
                for (int j = 0; j < 4; j++) cp16(sp + aso[j], agp[j] + ko);
#pragma unroll
                for (int j = 0; j < 4; j++) cp16(sp + bso[j], bgp[j] + ko * ND);
            }
            cp_commit();
        }
#pragma unroll
        for (int ks = 0; ks < 2; ks++)
#pragma unroll
            for (int mt = 0; mt < 4; mt++)
#pragma unroll
                for (int nb = 0; nb < 4; nb++) {
                    mma_f16(c[mt][nb * 2 + 0], af[ks][mt], &bf[ks][nb][0]);
                    mma_f16(c[mt][nb * 2 + 1], af[ks][mt], &bf[ks][nb][2]);
                }

        // ======== k-tile kt+1 (slot1) ========
#pragma unroll
        for (int ks = 0; ks < 2; ks++)
#pragma unroll
            for (int mt = 0; mt < 4; mt++)
                ldsm_x4(af[ks][mt][0], af[ks][mt][1], af[ks][mt][2], af[ks][mt][3],
                        sb1 + a_addr[mt] + ks * 32);
#pragma unroll
        for (int ks = 0; ks < 2; ks++)
#pragma unroll
            for (int nb = 0; nb < 4; nb++)
                ldsm_x4_t(bf[ks][nb][0], bf[ks][nb][1], bf[ks][nb][2], bf[ks][nb][3],
                          sb1 + b_addr[ks][nb]);
        {
            int pk = kt + 5;
            if (pk < KT) {
                int st = slot + 5; if (st >= NSTAGE) st -= NSTAGE;
                uint32_t sp = sbase + st * STAGE_B;
                size_t ko = (size_t)pk * BK;
#pragma unroll
                for (int j = 0; j < 4; j++) cp16(sp + aso[j], agp[j] + ko);
#pragma unroll
                for (int j = 0; j < 4; j++) cp16(sp + bso[j], bgp[j] + ko * ND);
            }
            cp_commit();
        }
#pragma unroll
        for (int ks = 0; ks < 2; ks++)
#pragma unroll
            for (int mt = 0; mt < 4; mt++)
#pragma unroll
                for (int nb = 0; nb < 4; nb++) {
                    mma_f16(c[mt][nb * 2 + 0], af[ks][mt], &bf[ks][nb][0]);
                    mma_f16(c[mt][nb * 2 + 1], af[ks][mt], &bf[ks][nb][2]);
                }

        slot += 2; if (slot >= NSTAGE) slot -= NSTAGE;
    }

    // ---- epilogue ----
    const float* be = bias + (size_t)e * ND;
    const int bofs = tn * BN;
#pragma unroll
    for (int mt = 0; mt < 4; mt++) {
        int mrow = tm * BM + wr * 64 + mt * 16 + (lane >> 2);
#pragma unroll
        for (int half = 0; half < 2; half++) {
            int m = mrow + half * 8;
            if (m >= Me) continue;
            if (PHASE1) {
                __half* Hr = g_Hh + (size_t)(base + m) * ND + bofs;
#pragma unroll
                for (int nt = 0; nt < 8; nt++) {
                    int n = wc * 64 + nt * 8 + (lane & 3) * 2;
                    float v0 = c[mt][nt][half * 2 + 0] + be[bofs + n];
                    float v1 = c[mt][nt][half * 2 + 1] + be[bofs + n + 1];
                    __half2 h = __floats2half2_rn(gelu_exact(v0), gelu_exact(v1));
                    *reinterpret_cast<uint32_t*>(Hr + n) = *(uint32_t*)&h;
                }
            } else {
                int tok = g_tok[e * MAXN + m];
                float g = g_gate[e * MAXN + m];
                float* Or = Out + (size_t)tok * ND + bofs;
#pragma unroll
                for (int nt = 0; nt < 8; nt++) {
                    int n = wc * 64 + nt * 8 + (lane & 3) * 2;
                    atomicAdd(&Or[n],     g * (c[mt][nt][half * 2 + 0] + be[bofs + n]));
                    atomicAdd(&Or[n + 1], g * (c[mt][nt][half * 2 + 1] + be[bofs + n + 1]));
                }
            }
        }
    }
}

// ---------------- launch ----------------
extern "C" void kernel_launch(void* const* d_in, const int* in_sizes, int n_in,
                              void* d_out, int out_size) {
    const float* x  = (const float*)d_in[0];
    const float* Wr = (const float*)d_in[1];
    const float* br = (const float*)d_in[2];
    const float* W1 = (const float*)d_in[3];
    const float* b1 = (const float*)d_in[4];
    const float* W2 = (const float*)d_in[5];
    const float* b2 = (const float*)d_in[6];
    float* out = (float*)d_out;

    int N = in_sizes[0] / D_MODEL;   // 8192 tokens
    if (N > MAXN) N = MAXN;

    cudaFuncSetAttribute(moe_gemm_kernel<D_MODEL, D_FF, true>,
                         cudaFuncAttributeMaxDynamicSharedMemorySize, DSMEM_BYTES);
    cudaFuncSetAttribute(moe_gemm_kernel<D_FF, D_MODEL, false>,
                         cudaFuncAttributeMaxDynamicSharedMemorySize, DSMEM_BYTES);

    init_kernel<<<1, 32>>>();
    prep_kernel<<<4096, 256>>>(out, out_size, x, N, Wr, br, W1);
    scan_kernel<<<1, 1>>>();

    // GEMM1 + 512 W2-converter CTAs (tn == 32 column)
    dim3 g1(D_FF / BN + 1, (N + BM - 1) / BM, NEXP);
    moe_gemm_kernel<D_MODEL, D_FF, true><<<g1, NTHREADS, DSMEM_BYTES>>>(b1, nullptr, W2);

    dim3 g2(D_MODEL / BN, (N + BM - 1) / BM, NEXP);
    moe_gemm_kernel<D_FF, D_MODEL, false><<<g2, NTHREADS, DSMEM_BYTES>>>(b2, out, nullptr);
}

// round 13
// speedup vs baseline: 1.1928x; 1.1071x over previous
#include <cuda_runtime.h>
#include <cuda_fp16.h>
#include <cstdint>
#include <math.h>

#define D_MODEL 1024
#define D_FF    4096
#define NEXP    8
#define MAXN    8192
#define HROWS   (2*MAXN + 256)

#define BM 128
#define BN 128
#define BK 32
#define NTHREADS 128
#define A_STRIDE_B 80
#define A_TILE_B (BM * A_STRIDE_B)
#define B_ROW_B  (BN * 2)
#define B_TILE_B (BK * B_ROW_B)
#define STAGE_B  (A_TILE_B + B_TILE_B)   // 18432
#define NSTAGE 6
#define DSMEM_BYTES (NSTAGE * STAGE_B)   // 110592 -> 2 CTAs/SM

__device__ int    g_cnt[NEXP];
__device__ int    g_base[NEXP];
__device__ int    g_tok[NEXP * MAXN];
__device__ float  g_gate[NEXP * MAXN];
__device__ __half g_xh [(size_t)MAXN * D_MODEL];
__device__ __half g_W1h[(size_t)NEXP * D_MODEL * D_FF];
__device__ __half g_W2h[(size_t)NEXP * D_FF * D_MODEL];
__device__ __half g_Hh [(size_t)HROWS * D_FF];

__device__ __forceinline__ void mma_f16(float c[4], const uint32_t a[4], const uint32_t b[2]) {
    asm volatile(
        "mma.sync.aligned.m16n8k16.row.col.f32.f16.f16.f32 "
        "{%0,%1,%2,%3}, {%4,%5,%6,%7}, {%8,%9}, {%0,%1,%2,%3};"
        : "+f"(c[0]), "+f"(c[1]), "+f"(c[2]), "+f"(c[3])
        : "r"(a[0]), "r"(a[1]), "r"(a[2]), "r"(a[3]), "r"(b[0]), "r"(b[1]));
}
__device__ __forceinline__ void ldsm_x4(uint32_t& r0, uint32_t& r1, uint32_t& r2, uint32_t& r3,
                                        uint32_t saddr) {
    asm volatile("ldmatrix.sync.aligned.m8n8.x4.shared.b16 {%0,%1,%2,%3}, [%4];"
                 : "=r"(r0), "=r"(r1), "=r"(r2), "=r"(r3) : "r"(saddr));
}
__device__ __forceinline__ void ldsm_x4_t(uint32_t& r0, uint32_t& r1, uint32_t& r2, uint32_t& r3,
                                          uint32_t saddr) {
    asm volatile("ldmatrix.sync.aligned.m8n8.x4.trans.shared.b16 {%0,%1,%2,%3}, [%4];"
                 : "=r"(r0), "=r"(r1), "=r"(r2), "=r"(r3) : "r"(saddr));
}
__device__ __forceinline__ void cp16(uint32_t saddr, const void* g) {
    asm volatile("cp.async.cg.shared.global [%0], [%1], 16;" :: "r"(saddr), "l"(g) : "memory");
}
__device__ __forceinline__ void cp_commit() { asm volatile("cp.async.commit_group;" ::: "memory"); }
__device__ __forceinline__ void cp_wait2()  { asm volatile("cp.async.wait_group 2;" ::: "memory"); }

__device__ __forceinline__ float gelu_exact(float v) {
    return 0.5f * v * (1.0f + erff(v * 0.7071067811865476f));
}

__global__ void init_kernel() {
    if (threadIdx.x < NEXP) g_cnt[threadIdx.x] = 0;
}

// ---------------- fused prep: router | zero out | half x | half W1/W2 ----------------
__global__ void prep_kernel(float* __restrict__ out, int nout,
                            const float* __restrict__ x, int N,
                            const float* __restrict__ Wr, const float* __restrict__ br,
                            const float* __restrict__ W1, const float* __restrict__ W2) {
    const int b = blockIdx.x;
    const int tid = threadIdx.x;

    if (b < 1024) {
        int wg = b * 8 + (tid >> 5);
        int lane = tid & 31;
        if (wg >= N) return;
        const float* xr = x + (size_t)wg * D_MODEL;

        float acc[NEXP];
#pragma unroll
        for (int e = 0; e < NEXP; e++) acc[e] = 0.0f;
#pragma unroll
        for (int it = 0; it < D_MODEL / 128; it++) {
            int d = it * 128 + lane * 4;
            float4 xv = *reinterpret_cast<const float4*>(xr + d);
            const float xa[4] = { xv.x, xv.y, xv.z, xv.w };
#pragma unroll
            for (int q = 0; q < 4; q++) {
                const float4* w4 = reinterpret_cast<const float4*>(Wr + (size_t)(d + q) * NEXP);
                float4 w0 = w4[0], w1 = w4[1];
                acc[0] += xa[q] * w0.x; acc[1] += xa[q] * w0.y;
                acc[2] += xa[q] * w0.z; acc[3] += xa[q] * w0.w;
                acc[4] += xa[q] * w1.x; acc[5] += xa[q] * w1.y;
                acc[6] += xa[q] * w1.z; acc[7] += xa[q] * w1.w;
            }
        }
#pragma unroll
        for (int off = 16; off; off >>= 1)
#pragma unroll
            for (int e = 0; e < NEXP; e++)
                acc[e] += __shfl_xor_sync(0xffffffffu, acc[e], off);

        if (lane == 0) {
            float l[NEXP];
#pragma unroll
            for (int e = 0; e < NEXP; e++) l[e] = acc[e] + br[e];
            float m = l[0];
#pragma unroll
            for (int e = 1; e < NEXP; e++) m = fmaxf(m, l[e]);
            float p[NEXP], se = 0.0f;
#pragma unroll
            for (int e = 0; e < NEXP; e++) { p[e] = expf(l[e] - m); se += p[e]; }
            int i1 = 0; float v1 = p[0];
#pragma unroll
            for (int e = 1; e < NEXP; e++) if (p[e] > v1) { v1 = p[e]; i1 = e; }
            int i2 = -1; float v2 = -1.0f;
#pragma unroll
            for (int e = 0; e < NEXP; e++) if (e != i1 && p[e] > v2) { v2 = p[e]; i2 = e; }
            float p1 = v1 / se, p2 = v2 / se;
            float inv = 1.0f / (p1 + p2 + 1e-9f);
            float w1 = p1 * inv, w2 = p2 * inv;

            int pos = atomicAdd(&g_cnt[i1], 1);
            g_tok[i1 * MAXN + pos] = wg;  g_gate[i1 * MAXN + pos] = w1;
            pos = atomicAdd(&g_cnt[i2], 1);
            g_tok[i2 * MAXN + pos] = wg;  g_gate[i2 * MAXN + pos] = w2;
        }
    } else if (b < 1536) {
        int n4 = nout >> 2;
        float4 z = make_float4(0.f, 0.f, 0.f, 0.f);
        for (int i = (b - 1024) * 256 + tid; i < n4; i += 512 * 256)
            reinterpret_cast<float4*>(out)[i] = z;
    } else if (b < 2048) {
        int n4 = N * D_MODEL / 4;
        for (int i = (b - 1536) * 256 + tid; i < n4; i += 512 * 256) {
            float4 v = reinterpret_cast<const float4*>(x)[i];
            __half2 h0 = __floats2half2_rn(v.x, v.y);
            __half2 h1 = __floats2half2_rn(v.z, v.w);
            uint2 u = { *(uint32_t*)&h0, *(uint32_t*)&h1 };
            reinterpret_cast<uint2*>(g_xh)[i] = u;
        }
    } else {
        const int n4 = NEXP * D_MODEL * D_FF / 4;
        for (int i = (b - 2048) * 256 + tid; i < n4; i += 4096 * 256) {
            float4 v = reinterpret_cast<const float4*>(W1)[i];
            __half2 a0 = __floats2half2_rn(v.x, v.y);
            __half2 a1 = __floats2half2_rn(v.z, v.w);
            uint2 u = { *(uint32_t*)&a0, *(uint32_t*)&a1 };
            reinterpret_cast<uint2*>(g_W1h)[i] = u;
            float4 w = reinterpret_cast<const float4*>(W2)[i];
            __half2 b0 = __floats2half2_rn(w.x, w.y);
            __half2 b1 = __floats2half2_rn(w.z, w.w);
            uint2 t = { *(uint32_t*)&b0, *(uint32_t*)&b1 };
            reinterpret_cast<uint2*>(g_W2h)[i] = t;
        }
    }
}

__global__ void scan_kernel() {
    int b = 0;
#pragma unroll
    for (int e = 0; e < NEXP; e++) { g_base[e] = b; b += g_cnt[e]; }
}

// fragment load/mma macros (buffers are distinct named arrays to help the allocator)
#define LOADA(AF, SB, KS) \
    { _Pragma("unroll") \
      for (int mt = 0; mt < 4; mt++) \
          ldsm_x4(AF[mt][0], AF[mt][1], AF[mt][2], AF[mt][3], (SB) + a_addr[mt] + (KS) * 32); }
#define LOADB(BF, SB, KS) \
    { _Pragma("unroll") \
      for (int nb = 0; nb < 4; nb++) \
          ldsm_x4_t(BF[nb][0], BF[nb][1], BF[nb][2], BF[nb][3], (SB) + b_addr[KS][nb]); }
#define MMAB(AF, BF) \
    { _Pragma("unroll") \
      for (int mt = 0; mt < 4; mt++) \
          _Pragma("unroll") \
          for (int nb = 0; nb < 4; nb++) { \
              mma_f16(c[mt][nb * 2 + 0], AF[mt], &BF[nb][0]); \
              mma_f16(c[mt][nb * 2 + 1], AF[mt], &BF[nb][2]); \
          } }
#define PREFETCH(PK) \
    { int _pk = (PK); \
      if (_pk < KT) { \
          int _st = slot + ((PK) - kt); if (_st >= NSTAGE) _st -= NSTAGE; \
          uint32_t _sp = sbase + _st * STAGE_B; \
          size_t _ko = (size_t)_pk * BK; \
          _Pragma("unroll") \
          for (int j = 0; j < 4; j++) cp16(_sp + aso[j], agp[j] + _ko); \
          _Pragma("unroll") \
          for (int j = 0; j < 4; j++) cp16(_sp + bso[j], bgp[j] + _ko * ND); \
      } \
      cp_commit(); }

// ---------------- grouped GEMM: register-pipelined fragments, 6-stage smem ----------------
template<int KD, int ND, bool PHASE1>
__global__ void __launch_bounds__(NTHREADS, 2)
moe_gemm_kernel(const float* __restrict__ bias, float* __restrict__ Out) {
    const int e  = blockIdx.z;
    const int Me = g_cnt[e];
    const int tm = blockIdx.y;
    if (tm * BM >= Me) return;
    const int tn   = blockIdx.x;
    const int base = g_base[e];

    extern __shared__ char smem[];
    const uint32_t sbase = (uint32_t)__cvta_generic_to_shared(smem);

    const int tid = threadIdx.x;
    const __half* Aglob = PHASE1 ? g_xh : g_Hh;
    const __half* We    = (PHASE1 ? g_W1h : g_W2h) + (size_t)e * KD * ND;

    const __half* agp[4]; uint32_t aso[4];
#pragma unroll
    for (int j = 0; j < 4; j++) {
        int cid = tid + NTHREADS * j;
        int row = cid >> 2, ch = cid & 3;
        int m = tm * BM + row;
        size_t arow;
        if (PHASE1) arow = (size_t)g_tok[e * MAXN + (m < Me ? m : 0)];
        else { long r = (long)base + m; if (r >= HROWS) r = 0; arow = (size_t)r; }
        agp[j] = Aglob + arow * KD + ch * 8;
        aso[j] = row * A_STRIDE_B + ch * 16;
    }
    const __half* bgp[4]; uint32_t bso[4];
#pragma unroll
    for (int j = 0; j < 4; j++) {
        int cid = tid + NTHREADS * j;
        int krow = cid >> 4, c = cid & 15;
        bgp[j] = We + (size_t)krow * ND + tn * BN + c * 8;
        bso[j] = A_TILE_B + krow * B_ROW_B + ((c ^ (krow & 7)) << 4);
    }

    constexpr int KT = KD / BK;        // 32 / 128
    const int warp = tid >> 5, lane = tid & 31;
    const int wr = warp >> 1, wc = warp & 1;   // 2x2 warp grid; warp tile 64x64

    uint32_t a_addr[4];
#pragma unroll
    for (int mt = 0; mt < 4; mt++) {
        int row = wr * 64 + mt * 16 + (lane & 15);
        a_addr[mt] = row * A_STRIDE_B + (lane >> 4) * 16;
    }
    uint32_t b_addr[2][4];
#pragma unroll
    for (int ks = 0; ks < 2; ks++)
#pragma unroll
        for (int nb = 0; nb < 4; nb++) {
            int krow = ks * 16 + (lane & 15);
            int nc = wc * 8 + nb * 2 + (lane >> 4);
            b_addr[ks][nb] = A_TILE_B + krow * B_ROW_B + ((nc ^ (krow & 7)) << 4);
        }

    float c[4][8][4];
#pragma unroll
    for (int i = 0; i < 4; i++)
#pragma unroll
        for (int j = 0; j < 8; j++)
#pragma unroll
            for (int k = 0; k < 4; k++) c[i][j][k] = 0.0f;

    // prologue: stages 0..3 (4 groups)
#pragma unroll
    for (int s = 0; s < 4; s++) {
        uint32_t sb = sbase + s * STAGE_B;
        size_t ko = (size_t)s * BK;
#pragma unroll
        for (int j = 0; j < 4; j++) cp16(sb + aso[j], agp[j] + ko);
#pragma unroll
        for (int j = 0; j < 4; j++) cp16(sb + bso[j], bgp[j] + ko * ND);
        cp_commit();
    }

    uint32_t af0[4][4], bf0[4][4], af1[4][4], bf1[4][4];

    cp_wait2();            // stages 0,1 complete
    __syncthreads();
    LOADA(af0, sbase, 0);  // (stage 0, ks 0)
    LOADB(bf0, sbase, 0);

    int slot = 0;
    for (int kt = 0; kt < KT; kt += 2) {
        const uint32_t sb0 = sbase + slot * STAGE_B;
        const int slot1 = (slot + 1 == NSTAGE) ? 0 : slot + 1;
        const uint32_t sb1 = sbase + slot1 * STAGE_B;

        // h1 = (slot, ks1)
        LOADA(af1, sb0, 1);
        LOADB(bf1, sb0, 1);
        PREFETCH(kt + 4);
        MMAB(af0, bf0);            // h0, overlaps ldsm(h1)

        // h2 = (slot1, ks0)
        LOADA(af0, sb1, 0);
        LOADB(bf0, sb1, 0);
        MMAB(af1, bf1);            // h1, overlaps ldsm(h2)

        // h3 = (slot1, ks1)
        LOADA(af1, sb1, 1);
        LOADB(bf1, sb1, 1);
        PREFETCH(kt + 5);
        MMAB(af0, bf0);            // h2, overlaps ldsm(h3)

        // guarantee stage kt+2 complete, barrier before next iteration's slot reuse,
        // then pre-load next h0 = (slot+2, ks0); final MMA overlaps it
        cp_wait2();
        __syncthreads();
        if (kt + 2 < KT) {
            int slot2 = slot + 2; if (slot2 >= NSTAGE) slot2 -= NSTAGE;
            const uint32_t sb2 = sbase + slot2 * STAGE_B;
            LOADA(af0, sb2, 0);
            LOADB(bf0, sb2, 0);
        }
        MMAB(af1, bf1);            // h3, overlaps ldsm(next h0)

        slot += 2; if (slot >= NSTAGE) slot -= NSTAGE;
    }

    // ---- epilogue ----
    const float* be = bias + (size_t)e * ND;
    const int bofs = tn * BN;
#pragma unroll
    for (int mt = 0; mt < 4; mt++) {
        int mrow = tm * BM + wr * 64 + mt * 16 + (lane >> 2);
#pragma unroll
        for (int half = 0; half < 2; half++) {
            int m = mrow + half * 8;
            if (m >= Me) continue;
            if (PHASE1) {
                __half* Hr = g_Hh + (size_t)(base + m) * ND + bofs;
#pragma unroll
                for (int nt = 0; nt < 8; nt++) {
                    int n = wc * 64 + nt * 8 + (lane & 3) * 2;
                    float v0 = c[mt][nt][half * 2 + 0] + be[bofs + n];
                    float v1 = c[mt][nt][half * 2 + 1] + be[bofs + n + 1];
                    __half2 h = __floats2half2_rn(gelu_exact(v0), gelu_exact(v1));
                    *reinterpret_cast<uint32_t*>(Hr + n) = *(uint32_t*)&h;
                }
            } else {
                int tok = g_tok[e * MAXN + m];
                float g = g_gate[e * MAXN + m];
                float* Or = Out + (size_t)tok * ND + bofs;
#pragma unroll
                for (int nt = 0; nt < 8; nt++) {
                    int n = wc * 64 + nt * 8 + (lane & 3) * 2;
                    atomicAdd(&Or[n],     g * (c[mt][nt][half * 2 + 0] + be[bofs + n]));
                    atomicAdd(&Or[n + 1], g * (c[mt][nt][half * 2 + 1] + be[bofs + n + 1]));
                }
            }
        }
    }
}

// ---------------- launch ----------------
extern "C" void kernel_launch(void* const* d_in, const int* in_sizes, int n_in,
                              void* d_out, int out_size) {
    const float* x  = (const float*)d_in[0];
    const float* Wr = (const float*)d_in[1];
    const float* br = (const float*)d_in[2];
    const float* W1 = (const float*)d_in[3];
    const float* b1 = (const float*)d_in[4];
    const float* W2 = (const float*)d_in[5];
    const float* b2 = (const float*)d_in[6];
    float* out = (float*)d_out;

    int N = in_sizes[0] / D_MODEL;   // 8192 tokens
    if (N > MAXN) N = MAXN;

    cudaFuncSetAttribute(moe_gemm_kernel<D_MODEL, D_FF, true>,
                         cudaFuncAttributeMaxDynamicSharedMemorySize, DSMEM_BYTES);
    cudaFuncSetAttribute(moe_gemm_kernel<D_FF, D_MODEL, false>,
                         cudaFuncAttributeMaxDynamicSharedMemorySize, DSMEM_BYTES);

    init_kernel<<<1, 32>>>();
    prep_kernel<<<6144, 256>>>(out, out_size, x, N, Wr, br, W1, W2);
    scan_kernel<<<1, 1>>>();

    dim3 g1(D_FF / BN, (N + BM - 1) / BM, NEXP);
    moe_gemm_kernel<D_MODEL, D_FF, true><<<g1, NTHREADS, DSMEM_BYTES>>>(b1, nullptr);

    dim3 g2(D_MODEL / BN, (N + BM - 1) / BM, NEXP);
    moe_gemm_kernel<D_FF, D_MODEL, false><<<g2, NTHREADS, DSMEM_BYTES>>>(b2, out);
}